// round 17
// baseline (speedup 1.0000x reference)
#include <cuda_runtime.h>
#include <math.h>

#define B   8
#define C   64
#define NP  65536
#define RR  32
#define R3  32768   // 32^3

#define NBLK   1024        // stats-kernel grid (128 chunks per batch)
#define CHUNKS 128         // chunks per batch
#define CPTS   512         // points per chunk

// Scratch (device globals — no allocation allowed in kernel_launch).
__device__ __align__(256) float g_scratch[(size_t)B * R3 * C]; // [B][R3][C]
__device__ __align__(256) float g_cnt[B * R3];                 // per-voxel counts
__device__ float g_maxsq[B];                      // atomicMax accumulator
__device__ float g_mean[B * 4];                   // per-batch mean (x,y,z)
__device__ float g_part[B * CHUNKS * 3];          // partial sums for mean

// Per-batch software barrier (stats kernel, 1 slot). cnt and gen on separate
// 128B lines. Replay-safe: gen monotone, cnt resets after use.
#define BARS 32            // uints per slot = 128B
__device__ unsigned g_barcnt[B * BARS];
__device__ unsigned g_bargen[B * BARS];

// Scatter -> finalize per-batch progress (padded to own lines).
// g_done[b]: scatter blocks completed for batch b (0..512).
// g_finarr[b]: finalize blocks arrived for batch b (reset bookkeeping).
__device__ unsigned g_done[B * BARS];
__device__ unsigned g_finarr[B * BARS];

__device__ __forceinline__ unsigned ld_acq(const unsigned* p) {
    unsigned v;
    asm volatile("ld.acquire.gpu.u32 %0, [%1];" : "=r"(v) : "l"(p));
    return v;
}

// Barrier over the 128 stats blocks of one batch.
__device__ __forceinline__ void batch_barrier(int b) {
    __syncthreads();
    if (threadIdx.x == 0) {
        __threadfence();
        unsigned* cnt = &g_barcnt[b * BARS];
        unsigned* gen = &g_bargen[b * BARS];
        const unsigned g0 = ld_acq(gen);                   // snapshot BEFORE arrive
        const unsigned old = atomicAdd(cnt, 1u);
        if (old == CHUNKS - 1) {
            atomicExch(cnt, 0u);                           // reset for next launch
            atomicAdd(gen, 1u);                            // release
        } else {
            int ns = 64;
            while (ld_acq(gen) == g0) { __nanosleep(ns); if (ns < 1024) ns <<= 1; }
        }
        __threadfence();
    }
    __syncthreads();
}

// ---------------------------------------------------------------------------
// K1: stats + scratch-zero kernel. Grid = 1024 blocks x 256 threads.
// __launch_bounds__(256, 7): 7 blocks/SM co-resident (1036 >= 1024) for the
// barrier. Coords staged in smem; ONE barrier only (nc/flat/count moved to
// scatter).
//   Phase A: load coords -> smem; partial sums -> g_part; zero cnt slice
//   ── batch barrier ──
//   Phase B: re-reduce own batch's 128 partials -> mean (identical per block)
//   Phase C: local max ||c-mean||^2 (smem) -> atomicMax(g_maxsq[b])
//   PDL trigger (scatter may launch; it only reads inputs until its sync)
//   Tail:    zero own 64KB scratch slice — overlapped with scatter's loads
// ---------------------------------------------------------------------------
__global__ __launch_bounds__(256, 7) void stats_kernel(
        const float* __restrict__ coords) {
    const int b     = blockIdx.x >> 7;
    const int chunk = blockIdx.x & (CHUNKS - 1);
    const int t     = threadIdx.x;            // 256
    const int base  = chunk * CPTS;
    const float* cb = coords + (size_t)b * 3 * NP;

    __shared__ float scx[CPTS], scy[CPTS], scz[CPTS];   // 6KB coord cache
    __shared__ float wx[8], wy[8], wz[8];
    __shared__ float s_mean[3];

    // ---- Phase A: load coords into smem + partial sums ----
    {
        const int i1 = base + t, i2 = base + t + 256;
        const float x1 = cb[i1],          x2 = cb[i2];
        const float y1 = cb[NP + i1],     y2 = cb[NP + i2];
        const float z1 = cb[2 * NP + i1], z2 = cb[2 * NP + i2];
        scx[t] = x1; scx[t + 256] = x2;
        scy[t] = y1; scy[t + 256] = y2;
        scz[t] = z1; scz[t + 256] = z2;

        float sx = x1 + x2, sy = y1 + y2, sz = z1 + z2;
#pragma unroll
        for (int s = 16; s > 0; s >>= 1) {
            sx += __shfl_down_sync(0xFFFFFFFFu, sx, s);
            sy += __shfl_down_sync(0xFFFFFFFFu, sy, s);
            sz += __shfl_down_sync(0xFFFFFFFFu, sz, s);
        }
        if ((t & 31) == 0) { wx[t >> 5] = sx; wy[t >> 5] = sy; wz[t >> 5] = sz; }
        __syncthreads();
        if (t == 0) {
            float ax = 0.f, ay = 0.f, az = 0.f;
#pragma unroll
            for (int w = 0; w < 8; w++) { ax += wx[w]; ay += wy[w]; az += wz[w]; }
            float* p = g_part + ((size_t)b * CHUNKS + chunk) * 3;
            p[0] = ax; p[1] = ay; p[2] = az;
            if (chunk == 0) g_maxsq[b] = 0.0f;   // zero accumulator (pre-barrier)
        }
        // zero own g_cnt slice (1KB) — consumed by scatter's count atomics
        // (ordered by the kernel boundary / gridDepSync).
        g_cnt[blockIdx.x * 256 + t] = 0.0f;
    }
    batch_barrier(b);

    // ---- Phase B: mean from the 128 partials (identical in all blocks) ----
    {
        __shared__ float rx[4], ry[4], rz[4];
        if (t < 128) {
            const float* p = g_part + ((size_t)b * CHUNKS + t) * 3;
            float px = p[0], py = p[1], pz = p[2];
#pragma unroll
            for (int s = 16; s > 0; s >>= 1) {
                px += __shfl_down_sync(0xFFFFFFFFu, px, s);
                py += __shfl_down_sync(0xFFFFFFFFu, py, s);
                pz += __shfl_down_sync(0xFFFFFFFFu, pz, s);
            }
            if ((t & 31) == 0) { rx[t >> 5] = px; ry[t >> 5] = py; rz[t >> 5] = pz; }
        }
        __syncthreads();
        if (t == 0) {
            s_mean[0] = (rx[0] + rx[1] + rx[2] + rx[3]) / (float)NP;
            s_mean[1] = (ry[0] + ry[1] + ry[2] + ry[3]) / (float)NP;
            s_mean[2] = (rz[0] + rz[1] + rz[2] + rz[3]) / (float)NP;
            if (chunk == 0) {                 // publish mean for scatter
                g_mean[b * 4 + 0] = s_mean[0];
                g_mean[b * 4 + 1] = s_mean[1];
                g_mean[b * 4 + 2] = s_mean[2];
            }
        }
        __syncthreads();
    }
    const float mx = s_mean[0], my = s_mean[1], mz = s_mean[2];

    // ---- Phase C: max squared norm over this block's 512 points (smem) ----
    {
        float m = 0.f;
#pragma unroll
        for (int k = 0; k < 2; k++) {
            int i = t + k * 256;
            float x = scx[i] - mx;
            float y = scy[i] - my;
            float z = scz[i] - mz;
            m = fmaxf(m, x * x + y * y + z * z);
        }
#pragma unroll
        for (int s = 16; s > 0; s >>= 1)
            m = fmaxf(m, __shfl_down_sync(0xFFFFFFFFu, m, s));
        if ((t & 31) == 0) wx[t >> 5] = m;
        __syncthreads();
        if (t == 0) {
#pragma unroll
            for (int w = 1; w < 8; w++) m = fmaxf(m, wx[w]);
            atomicMax((unsigned*)&g_maxsq[b], __float_as_uint(m));
        }
    }

    // ---- PDL: scatter may launch; it only reads inputs until its sync. ----
#if __CUDA_ARCH__ >= 900
    cudaTriggerProgrammaticLaunchCompletion();
#endif

    // ---- Tail: zero own scratch slice (64KB). Overlaps scatter's loads. ----
    {
        const float4 z4 = make_float4(0.f, 0.f, 0.f, 0.f);
        float4* zs = (float4*)(g_scratch + (size_t)blockIdx.x * (R3 * C / CHUNKS));
#pragma unroll
        for (int k = 0; k < 16; k++) zs[t + k * 256] = z4;
    }
}

// ---------------------------------------------------------------------------
// K2: scatter — now also computes nc / flat ids / counts (Phase D moved here;
// it hides under the feature-load latency). PDL secondary of stats.
//   Pre-sync:  feature tile -> smem (__ldcs) AND coord loads (inputs only).
//   gridDepSync (stats complete: mean/maxsq/zeroed cnt+scratch visible).
//   Mid:       nc stores, flat ids, count atomics; publish not yet.
//   PDL trigger (finalize may launch; gated by g_done counters).
//   Phase 2:   line-coalesced red.v4 atomics into scratch.
//   End:       threadfence + g_done[b]++ (finalize progress gate).
// ---------------------------------------------------------------------------
#define TPTS 128           // points per block
#define TSTR 68            // smem row stride in floats (272B = 17*16B)

__global__ __launch_bounds__(256) void scatter_kernel(
        const float* __restrict__ features,
        const float* __restrict__ coords,
        float* __restrict__ nc_out) {
    const int blk = blockIdx.x;               // B * NP / TPTS = 4096
    const int b   = blk >> 9;                 // 512 blocks per batch
    const int n0  = (blk & 511) * TPTS;
    const int t   = threadIdx.x;              // 256

    __shared__ __align__(16) float tile[TPTS * TSTR];
    __shared__ int sflat[TPTS];

    // ---- Pre-sync: feature tile -> smem (input-only, overlaps stats tail) ----
    {
        const int p  = t & (TPTS - 1);        // point within tile
        const int ch = (t >> 7) * 8;          // channel-quad base: 0 or 8
        const float* f = features + (size_t)b * C * NP + n0 + p;
#pragma unroll
        for (int q = 0; q < 8; q++) {
            const int c = (ch + q) * 4;
            float4 v;
            v.x = __ldcs(f + (size_t)(c + 0) * NP);
            v.y = __ldcs(f + (size_t)(c + 1) * NP);
            v.z = __ldcs(f + (size_t)(c + 2) * NP);
            v.w = __ldcs(f + (size_t)(c + 3) * NP);
            *(float4*)&tile[p * TSTR + c] = v;
        }
    }
    // Coord loads for this block's 128 points (inputs — also pre-sync).
    float cx = 0.f, cy = 0.f, cz = 0.f;
    const float* cb = coords + (size_t)b * 3 * NP;
    if (t < TPTS) {
        cx = cb[n0 + t];
        cy = cb[NP + n0 + t];
        cz = cb[2 * NP + n0 + t];
    }

    // ---- Wait for stats (mean, maxsq, zeroed cnt + scratch) ----
#if __CUDA_ARCH__ >= 900
    cudaGridDependencySynchronize();
#endif

    if (t < TPTS) {
        const float mx = g_mean[b * 4 + 0];
        const float my = g_mean[b * 4 + 1];
        const float mz = g_mean[b * 4 + 2];
        const float sc = (float)RR / (2.0f * sqrtf(g_maxsq[b]));   // EPS = 0

        float x = fminf(fmaxf(fmaf(cx - mx, sc, 16.0f), 0.0f), 31.0f);
        float y = fminf(fmaxf(fmaf(cy - my, sc, 16.0f), 0.0f), 31.0f);
        float z = fminf(fmaxf(fmaf(cz - mz, sc, 16.0f), 0.0f), 31.0f);

        float* nb = nc_out + (size_t)b * 3 * NP;
        __stcs(&nb[n0 + t],          x);
        __stcs(&nb[NP + n0 + t],     y);
        __stcs(&nb[2 * NP + n0 + t], z);

        // jnp.round == round-half-to-even == rintf
        const int flat = ((int)rintf(x) * RR + (int)rintf(y)) * RR + (int)rintf(z);
        sflat[t] = flat;
        atomicAdd(&g_cnt[b * R3 + flat], 1.0f);
    }

    // ---- PDL: finalize may launch; g_done counters gate its reads. ----
#if __CUDA_ARCH__ >= 900
    cudaTriggerProgrammaticLaunchCompletion();
#endif
    __syncthreads();

    // ---- Phase 2: coalesced-lane reds (lanes 0-15 point A, 16-31 point B) ----
    {
        const int w    = t >> 5;              // warp 0..7, 16 points each
        const int l    = t & 31;
        const int half = l >> 4;              // 0 -> point A, 1 -> point B
        const int lc   = (l & 15) * 4;        // channel offset
        float* sbase = g_scratch + (size_t)b * R3 * C;
#pragma unroll
        for (int i = 0; i < 8; i++) {
            const int p = w * 16 + 2 * i + half;
            const int flat = sflat[p];
            const float4 v = *(const float4*)&tile[p * TSTR + lc];
            float* dst = sbase + (size_t)flat * C + lc;
            asm volatile("red.global.add.v4.f32 [%0], {%1, %2, %3, %4};"
                         :: "l"(dst), "f"(v.x), "f"(v.y), "f"(v.z), "f"(v.w)
                         : "memory");
        }
    }

    // ---- Publish completion for this batch ----
    __threadfence();
    __syncthreads();
    if (t == 0) atomicAdd(&g_done[b * BARS], 1u);
}

// ---------------------------------------------------------------------------
// K3: finalize — normalize by count + transpose [B][R3][C] -> [B][C][R3].
// PDL secondary of scatter: spins until its batch's 512 scatter blocks are
// done (CTA dispatch is FIFO across in-stream grids -> no deadlock), so
// finalize of batch 0 overlaps scatter of batches 1-7.
// ---------------------------------------------------------------------------
__global__ __launch_bounds__(256) void finalize_kernel(float* __restrict__ out) {
    const int blk = blockIdx.x;               // B * R3 / 64 = 4096
    const int b   = blk >> 9;                 // 512 blocks per batch
    const int v0  = (blk & 511) * 64;
    const int t   = threadIdx.x;              // 256

    __shared__ float tile[64 * 65];
    __shared__ float inv[64];

#if __CUDA_ARCH__ >= 900
    // Allow upstream to be still in flight; gate on per-batch progress.
#endif
    if (t == 0) {
        int ns = 64;
        while (ld_acq(&g_done[b * BARS]) < 512u) {
            __nanosleep(ns); if (ns < 2048) ns <<= 1;
        }
        __threadfence();
    }
    __syncthreads();

    const float4* src = (const float4*)(g_scratch + ((size_t)b * R3 + v0) * C);
#pragma unroll
    for (int it = 0; it < 4; it++) {
        const int i = t + it * 256;           // float4 index (1024 total)
        const float4 u = src[i];
        const int g = i * 4;
        const int v = g >> 6, c = g & 63;
        tile[v * 65 + c + 0] = u.x;
        tile[v * 65 + c + 1] = u.y;
        tile[v * 65 + c + 2] = u.z;
        tile[v * 65 + c + 3] = u.w;
    }
    if (t < 64) inv[t] = 1.0f / fmaxf(g_cnt[b * R3 + v0 + t], 1.0f);
    __syncthreads();

    float* dst = out + (size_t)b * C * R3 + v0;
#pragma unroll
    for (int it = 0; it < 4; it++) {
        const int i = t + it * 256;
        const int g = i * 4;
        const int c = g >> 6, v = g & 63;
        float4 r;
        r.x = tile[(v + 0) * 65 + c] * inv[v + 0];
        r.y = tile[(v + 1) * 65 + c] * inv[v + 1];
        r.z = tile[(v + 2) * 65 + c] * inv[v + 2];
        r.w = tile[(v + 3) * 65 + c] * inv[v + 3];
        __stcs((float4*)&dst[(size_t)c * R3 + v], r);
    }

    // ---- Reset per-batch counters for the next graph replay ----
    if (t == 0) {
        const unsigned o = atomicAdd(&g_finarr[b * BARS], 1u);
        if (o == 511u) {                      // last finalize block of batch b
            atomicExch(&g_done[b * BARS], 0u);
            atomicExch(&g_finarr[b * BARS], 0u);
        }
    }
}

// ---------------------------------------------------------------------------
extern "C" void kernel_launch(void* const* d_in, const int* in_sizes, int n_in,
                              void* d_out, int out_size) {
    const float* features = (const float*)d_in[0];
    const float* coords   = (const float*)d_in[1];
    if (n_in >= 2 && in_sizes[0] < in_sizes[1]) {
        features = (const float*)d_in[1];
        coords   = (const float*)d_in[0];
    }

    float* out    = (float*)d_out;
    float* nc_out = out + (size_t)B * C * R3;   // nc follows vox_feat in d_out

    stats_kernel<<<NBLK, 256>>>(coords);

    // Scatter with PDL: starts while stats drains its zero-store tail.
    {
        cudaLaunchConfig_t cfg = {};
        cfg.gridDim  = dim3((B * NP) / TPTS, 1, 1);
        cfg.blockDim = dim3(256, 1, 1);
        cudaLaunchAttribute attr[1];
        attr[0].id = cudaLaunchAttributeProgrammaticStreamSerialization;
        attr[0].val.programmaticStreamSerializationAllowed = 1;
        cfg.attrs = attr;
        cfg.numAttrs = 1;
        cudaLaunchKernelEx(&cfg, scatter_kernel, features, coords, nc_out);
    }

    // Finalize with PDL: per-batch spin on g_done lets batch 0 finalize while
    // later batches are still scattering.
    {
        cudaLaunchConfig_t cfg = {};
        cfg.gridDim  = dim3((B * R3) / 64, 1, 1);
        cfg.blockDim = dim3(256, 1, 1);
        cudaLaunchAttribute attr[1];
        attr[0].id = cudaLaunchAttributeProgrammaticStreamSerialization;
        attr[0].val.programmaticStreamSerializationAllowed = 1;
        cfg.attrs = attr;
        cfg.numAttrs = 1;
        cudaLaunchKernelEx(&cfg, finalize_kernel, out);
    }
}